// round 3
// baseline (speedup 1.0000x reference)
#include <cuda_runtime.h>

// MultiHeadAttentionQuantum — closed-form reduction (R1 derivation):
//   c_u = cos(q_u + phi_u);  out_w = prod_{u<=w} c_u (w>=1);  out_0 = prod_{u=1..7} c_u
//   y = Wc @ out + bc.  k/v are dead code in the reference.
//
// R3: one token per 8 lanes (lane handles wire u). 262144 threads -> ~55 warps/SM
// to hide DRAM latency (was ~7). No smem, no barrier; per-lane row-u weight loads
// (warp-broadcast), feature/cos exchange via __shfl_sync width-8.

#define E_DIM 8

__global__ __launch_bounds__(256)
void mhaq_kernel(const float* __restrict__ x,
                 const float* __restrict__ Wq, const float* __restrict__ bq,
                 const float* __restrict__ Wc, const float* __restrict__ bc,
                 const float* __restrict__ phi,
                 float* __restrict__ out)
{
    const unsigned FULL = 0xFFFFFFFFu;
    int gtid = blockIdx.x * blockDim.x + threadIdx.x;   // grid sized exactly
    int u = gtid & 7;                                   // wire index
    int t = gtid >> 3;                                  // token index

    // Issue all global loads up front (max MLP): this lane's feature + its
    // weight rows. Row-u loads are warp-broadcast (8 distinct lines max).
    float xu = __ldg(&x[t * E_DIM + u]);
    const float4* Wq4 = reinterpret_cast<const float4*>(Wq);
    const float4* Wc4 = reinterpret_cast<const float4*>(Wc);
    float4 wq0 = __ldg(&Wq4[u * 2]);
    float4 wq1 = __ldg(&Wq4[u * 2 + 1]);
    float4 wc0 = __ldg(&Wc4[u * 2]);
    float4 wc1 = __ldg(&Wc4[u * 2 + 1]);
    float base = __ldg(&bq[u]) + __ldg(&phi[u]);
    float bcu  = __ldg(&bc[u]);

    // Gather all 8 features of this token (width-8 shuffle subgroups).
    float xr[8];
    #pragma unroll
    for (int e = 0; e < 8; e++) xr[e] = __shfl_sync(FULL, xu, e, 8);

    // q_u = Wq[u,:] @ x + bq_u + phi_u ;  c_u = cos(q_u)
    float qv = base;
    qv = fmaf(wq0.x, xr[0], qv); qv = fmaf(wq0.y, xr[1], qv);
    qv = fmaf(wq0.z, xr[2], qv); qv = fmaf(wq0.w, xr[3], qv);
    qv = fmaf(wq1.x, xr[4], qv); qv = fmaf(wq1.y, xr[5], qv);
    qv = fmaf(wq1.z, xr[6], qv); qv = fmaf(wq1.w, xr[7], qv);
    float cu = __cosf(qv);

    // Gather all 8 cosines; compute all prefix products locally (no 3rd round).
    float c[8];
    #pragma unroll
    for (int e = 0; e < 8; e++) c[e] = __shfl_sync(FULL, cu, e, 8);

    float o[8];
    float pre = c[0];
    #pragma unroll
    for (int w = 1; w < 8; w++) { pre *= c[w]; o[w] = pre; }
    float suf = c[1];
    #pragma unroll
    for (int w = 2; w < 8; w++) suf *= c[w];
    o[0] = suf;

    // y_u = Wc[u,:] @ o + bc_u
    float y = bcu;
    y = fmaf(wc0.x, o[0], y); y = fmaf(wc0.y, o[1], y);
    y = fmaf(wc0.z, o[2], y); y = fmaf(wc0.w, o[3], y);
    y = fmaf(wc1.x, o[4], y); y = fmaf(wc1.y, o[5], y);
    y = fmaf(wc1.z, o[6], y); y = fmaf(wc1.w, o[7], y);

    out[t * E_DIM + u] = y;   // coalesced
}

extern "C" void kernel_launch(void* const* d_in, const int* in_sizes, int n_in,
                              void* d_out, int out_size)
{
    // metadata order: x, Wq, bq, Wk, bk, Wv, bv, Wc, bc, phi
    const float* x   = (const float*)d_in[0];
    const float* Wq  = (const float*)d_in[1];
    const float* bq  = (const float*)d_in[2];
    const float* Wc  = (const float*)d_in[7];
    const float* bc  = (const float*)d_in[8];
    const float* phi = (const float*)d_in[9];
    float* out = (float*)d_out;

    int n_tok = in_sizes[0] / E_DIM;          // 32768
    int total = n_tok * E_DIM;                // 262144 lanes
    int threads = 256;
    int blocks = total / threads;             // 1024 (exact)
    mhaq_kernel<<<blocks, threads>>>(x, Wq, bq, Wc, bc, phi, out);
}